// round 3
// baseline (speedup 1.0000x reference)
#include <cuda_runtime.h>
#include <cuda_bf16.h>
#include <cstdint>
#include <cstddef>

// ---------------------------------------------------------------------------
// d[n,c] = ||x_n||^2 + ||p_c||^2 - 2 * <x_n, p_c>
// x: [16384,1024] f32, p: [4096,1024] f32, out: [16384,4096] f32
// Path: bf16 HMMA (mma.sync m16n8k16) for the cross term; fp32 norms; fused
// epilogue. tcgen05 is unavailable (ptxas target is plain sm_103).
// ---------------------------------------------------------------------------

static constexpr int N_ROWS = 16384;
static constexpr int C_ROWS = 4096;
static constexpr int DDIM   = 1024;

static constexpr int TILE_M = 128;
static constexpr int TILE_N = 128;
static constexpr int TILE_K = 64;                       // 64 bf16 = 128 B/row
static constexpr int K_TILES = DDIM / TILE_K;           // 16
static constexpr int STAGES  = 4;

static constexpr int A_STAGE_BYTES = TILE_M * TILE_K * 2;   // 16384
static constexpr int B_STAGE_BYTES = TILE_N * TILE_K * 2;   // 16384
static constexpr int STAGE_BYTES   = A_STAGE_BYTES + B_STAGE_BYTES;  // 32768
static constexpr unsigned SMEM_DYN = STAGES * STAGE_BYTES;  // 131072

// ---------------- device scratch (allocations are forbidden) ---------------
__device__ __align__(128) __nv_bfloat16 g_A[(size_t)N_ROWS * DDIM];   // 32 MB
__device__ __align__(128) __nv_bfloat16 g_B[(size_t)C_ROWS * DDIM];   //  8 MB
__device__ float g_xsq[N_ROWS];
__device__ float g_psq[C_ROWS];

// ------------------------------ helpers ------------------------------------
__device__ __forceinline__ uint32_t s2u(const void* p) {
    return (uint32_t)__cvta_generic_to_shared(p);
}
// XOR swizzle on 128-byte rows: flips bits[6:4] with bits[9:7] (row % 8).
__device__ __forceinline__ uint32_t swz(uint32_t o) { return o ^ ((o >> 3) & 0x70u); }

__device__ __forceinline__ uint32_t pack2(float a, float b) {
    __nv_bfloat162 h = __floats2bfloat162_rn(a, b);
    return *reinterpret_cast<uint32_t*>(&h);
}
__device__ __forceinline__ void cp16(uint32_t dst, const void* src) {
    asm volatile("cp.async.cg.shared.global [%0], [%1], 16;"
                 :: "r"(dst), "l"(src) : "memory");
}
__device__ __forceinline__ void cp_commit() {
    asm volatile("cp.async.commit_group;" ::: "memory");
}
template <int N>
__device__ __forceinline__ void cp_wait() {
    asm volatile("cp.async.wait_group %0;" :: "n"(N) : "memory");
}
__device__ __forceinline__ void ldm_x4(uint32_t* r, uint32_t addr) {
    asm volatile("ldmatrix.sync.aligned.m8n8.x4.shared.b16 {%0,%1,%2,%3}, [%4];"
                 : "=r"(r[0]), "=r"(r[1]), "=r"(r[2]), "=r"(r[3]) : "r"(addr));
}
__device__ __forceinline__ void mma16816(float* c, const uint32_t* a,
                                         uint32_t b0, uint32_t b1) {
    asm volatile(
        "mma.sync.aligned.m16n8k16.row.col.f32.bf16.bf16.f32 "
        "{%0,%1,%2,%3}, {%4,%5,%6,%7}, {%8,%9}, {%0,%1,%2,%3};"
        : "+f"(c[0]), "+f"(c[1]), "+f"(c[2]), "+f"(c[3])
        : "r"(a[0]), "r"(a[1]), "r"(a[2]), "r"(a[3]), "r"(b0), "r"(b1));
}

// ---------------- pre-pass: f32 -> bf16 (row-major) + row norms ------------
__global__ void __launch_bounds__(128)
conv_kernel(const float* __restrict__ src, __nv_bfloat16* __restrict__ dst,
            float* __restrict__ sq) {
    const int row  = blockIdx.x * 4 + (threadIdx.x >> 5);
    const int lane = threadIdx.x & 31;
    const float4* xr = reinterpret_cast<const float4*>(src + (size_t)row * DDIM);
    uint4* dr = reinterpret_cast<uint4*>(dst + (size_t)row * DDIM);
    float ss = 0.f;
#pragma unroll
    for (int j = 0; j < 4; j++) {
        const int c8 = lane + j * 32;              // 8-elem chunk, 0..127
        float4 f0 = xr[2 * c8];
        float4 f1 = xr[2 * c8 + 1];
        ss += f0.x * f0.x + f0.y * f0.y + f0.z * f0.z + f0.w * f0.w
            + f1.x * f1.x + f1.y * f1.y + f1.z * f1.z + f1.w * f1.w;
        uint4 v;
        v.x = pack2(f0.x, f0.y); v.y = pack2(f0.z, f0.w);
        v.z = pack2(f1.x, f1.y); v.w = pack2(f1.z, f1.w);
        dr[c8] = v;
    }
#pragma unroll
    for (int o = 16; o; o >>= 1) ss += __shfl_xor_sync(0xffffffffu, ss, o);
    if (lane == 0) sq[row] = ss;
}

// --------------------------- main GEMM kernel ------------------------------
// CTA: 256 threads = 8 warps in a 2(M) x 4(N) grid; warp tile 64x32.
// Smem per stage: A[128][64] + B[128][64] bf16, 128B rows, XOR-swizzled.
__device__ __forceinline__ void issue_stage(uint32_t sA, uint32_t sB,
                                            const __nv_bfloat16* Ag,
                                            const __nv_bfloat16* Bg,
                                            int kt, int tid) {
    const size_t kof = (size_t)kt * TILE_K;
#pragma unroll
    for (int i = 0; i < 4; i++) {                  // 1024 16B chunks / 256 thr
        const int id  = tid + i * 256;
        const int row = id >> 3;                   // 0..127
        const int c16 = id & 7;                    // 16B unit within 128B row
        cp16(sA + swz((uint32_t)(row * 128 + c16 * 16)),
             Ag + (size_t)row * DDIM + kof + c16 * 8);
        cp16(sB + swz((uint32_t)(row * 128 + c16 * 16)),
             Bg + (size_t)row * DDIM + kof + c16 * 8);
    }
    cp_commit();
}

__global__ void __launch_bounds__(256, 1)
gemm_kernel(float* __restrict__ out) {
    extern __shared__ char smem[];
    const uint32_t sbase = s2u(smem);

    const int tid  = threadIdx.x;
    const int wid  = tid >> 5;
    const int lane = tid & 31;
    const int wm = (wid & 1) * 64;                 // warp M offset in tile
    const int wn = (wid >> 1) * 32;                // warp N offset in tile

    const int m0 = blockIdx.x * TILE_M;
    const int n0 = blockIdx.y * TILE_N;
    const __nv_bfloat16* Ag = g_A + (size_t)m0 * DDIM;
    const __nv_bfloat16* Bg = g_B + (size_t)n0 * DDIM;

    float acc[4][4][4];
#pragma unroll
    for (int i = 0; i < 4; i++)
#pragma unroll
        for (int j = 0; j < 4; j++)
#pragma unroll
            for (int r = 0; r < 4; r++) acc[i][j][r] = 0.f;

    // prefetch stages 0..2
#pragma unroll
    for (int s = 0; s < STAGES - 1; s++)
        issue_stage(sbase + s * STAGE_BYTES,
                    sbase + s * STAGE_BYTES + A_STAGE_BYTES, Ag, Bg, s, tid);

    // ldmatrix lane address pattern: row = base + (lane&15), col-k += (lane>>4)*8
    const int lrow = lane & 15;
    const int lk   = (lane >> 4) * 8;

    for (int kt = 0; kt < K_TILES; kt++) {
        cp_wait<STAGES - 2>();
        __syncthreads();

        if (kt + STAGES - 1 < K_TILES) {
            const int s = (kt + STAGES - 1) % STAGES;
            issue_stage(sbase + s * STAGE_BYTES,
                        sbase + s * STAGE_BYTES + A_STAGE_BYTES,
                        Ag, Bg, kt + STAGES - 1, tid);
        }

        const uint32_t sA = sbase + (kt % STAGES) * STAGE_BYTES;
        const uint32_t sB = sA + A_STAGE_BYTES;

#pragma unroll
        for (int kk = 0; kk < 4; kk++) {           // 4 x k16 per 64-wide tile
            const int kc = kk * 16 + lk;
            uint32_t a[4][4], b[2][4];
#pragma unroll
            for (int mi = 0; mi < 4; mi++)
                ldm_x4(a[mi], sA + swz((uint32_t)((wm + mi * 16 + lrow) * 128 + kc * 2)));
#pragma unroll
            for (int nj = 0; nj < 2; nj++)
                ldm_x4(b[nj], sB + swz((uint32_t)((wn + nj * 16 + lrow) * 128 + kc * 2)));
#pragma unroll
            for (int mi = 0; mi < 4; mi++) {
#pragma unroll
                for (int nj = 0; nj < 2; nj++) {
                    mma16816(acc[mi][2 * nj + 0], a[mi], b[nj][0], b[nj][2]);
                    mma16816(acc[mi][2 * nj + 1], a[mi], b[nj][1], b[nj][3]);
                }
            }
        }
    }

    // ---------------- fused epilogue: out = fma(-2, acc, xsq + psq) --------
    const int tr = lane >> 2;                      // 0..7 row within m16n8
    const int tc = (lane & 3) * 2;                 // 0,2,4,6 col pair
#pragma unroll
    for (int mi = 0; mi < 4; mi++) {
        const int gm0 = m0 + wm + mi * 16 + tr;
        const float xs0 = g_xsq[gm0];
        const float xs1 = g_xsq[gm0 + 8];
        float* o0 = out + (size_t)gm0 * C_ROWS + n0 + wn;
        float* o1 = o0 + (size_t)8 * C_ROWS;
#pragma unroll
        for (int ni = 0; ni < 4; ni++) {
            const int gc = n0 + wn + ni * 8 + tc;
            const float pq0 = __ldg(g_psq + gc);
            const float pq1 = __ldg(g_psq + gc + 1);
            float2 r0, r1;
            r0.x = fmaf(-2.f, acc[mi][ni][0], xs0 + pq0);
            r0.y = fmaf(-2.f, acc[mi][ni][1], xs0 + pq1);
            r1.x = fmaf(-2.f, acc[mi][ni][2], xs1 + pq0);
            r1.y = fmaf(-2.f, acc[mi][ni][3], xs1 + pq1);
            *reinterpret_cast<float2*>(o0 + ni * 8 + tc) = r0;
            *reinterpret_cast<float2*>(o1 + ni * 8 + tc) = r1;
        }
    }
}

// ------------------------------- launch ------------------------------------
extern "C" void kernel_launch(void* const* d_in, const int* in_sizes, int n_in,
                              void* d_out, int out_size) {
    const float* x = (const float*)d_in[0];       // [16384, 1024]
    const float* p = (const float*)d_in[1];       // [4096, 1024]
    float* out = (float*)d_out;                   // [16384, 4096]

    __nv_bfloat16 *dA = nullptr, *dB = nullptr;
    float *dxsq = nullptr, *dpsq = nullptr;
    cudaGetSymbolAddress((void**)&dA,   g_A);
    cudaGetSymbolAddress((void**)&dB,   g_B);
    cudaGetSymbolAddress((void**)&dxsq, g_xsq);
    cudaGetSymbolAddress((void**)&dpsq, g_psq);

    cudaFuncSetAttribute(gemm_kernel,
                         cudaFuncAttributeMaxDynamicSharedMemorySize, SMEM_DYN);

    conv_kernel<<<N_ROWS / 4, 128>>>(x, dA, dxsq);
    conv_kernel<<<C_ROWS / 4, 128>>>(p, dB, dpsq);
    gemm_kernel<<<dim3(N_ROWS / TILE_M, C_ROWS / TILE_N), 256, SMEM_DYN>>>(out);
}